// round 3
// baseline (speedup 1.0000x reference)
#include <cuda_runtime.h>
#include <cuda_fp16.h>
#include <mma.h>

using namespace nvcuda;

// Problem shape (fixed by reference)
constexpr int B = 16;
constexpr int N = 2048;
constexpr int D = 512;

// Tiling
constexpr int BM = 64;     // query rows per CTA
constexpr int BN = 64;     // key rows per tile
constexpr int NWARP = 8;   // 256 threads
constexpr int NTILES = N / BN;   // 32
constexpr int MBLOCKS = N / BM;  // 32

// Padded smem leading dims (avoid ldmatrix bank conflicts)
constexpr int QLD = D + 8;    // 520 halfs -> 1040B row stride
constexpr int SLD = BN + 4;   // 68 floats (mult of 4 for wmma float store)
constexpr int PLD = BN + 8;   // 72 halfs

// Shared memory layout (bytes)
constexpr int OFF_Q  = 0;
constexpr int SZ_Q   = BM * QLD * 2;            // 66560
constexpr int OFF_K  = OFF_Q + SZ_Q;            // 66560
constexpr int SZ_K   = BN * QLD * 2;            // 66560
constexpr int OFF_S  = OFF_K + SZ_K;            // 133120
constexpr int SZ_S   = BM * SLD * 4;            // 17408
constexpr int OFF_P  = OFF_S + SZ_S;            // 150528
constexpr int SZ_P   = BM * PLD * 2;            // 9216
constexpr int OFF_KN = OFF_P + SZ_P;            // 159744
constexpr int OFF_L  = OFF_KN + 256;            // 160000
constexpr int SMEM_BYTES = OFF_L + 256;         // 160256
// Epilogue O staging aliases Q+K region: 8 warps * 64*64 floats = 131072 <= 133120. OK.

// Scratch: normalized x (fp16) and per-row L2 norms
__device__ __half xn_g[(size_t)B * N * D];
__device__ float  norm_g[B * N];

// ---------------------------------------------------------------------------
// Kernel 1: per-row L2 norm + fp16 normalize.  grid = B*N blocks, 128 threads.
// ---------------------------------------------------------------------------
__global__ void normalize_kernel(const float* __restrict__ x) {
    const int row = blockIdx.x;                 // [0, B*N)
    const float* xr = x + (size_t)row * D;
    const int t = threadIdx.x;                  // 128 threads * float4 = 512

    float4 v = reinterpret_cast<const float4*>(xr)[t];
    float s = v.x * v.x + v.y * v.y + v.z * v.z + v.w * v.w;
    #pragma unroll
    for (int o = 16; o > 0; o >>= 1) s += __shfl_down_sync(0xffffffffu, s, o);

    __shared__ float ws[4];
    __shared__ float inv_sh;
    if ((t & 31) == 0) ws[t >> 5] = s;
    __syncthreads();
    if (t == 0) {
        float tot = ws[0] + ws[1] + ws[2] + ws[3];
        float nm = sqrtf(tot);
        norm_g[row] = nm;
        inv_sh = 1.0f / fmaxf(nm, 1e-20f);
    }
    __syncthreads();
    const float inv = inv_sh;

    __half2* o2 = reinterpret_cast<__half2*>(xn_g + (size_t)row * D);
    o2[2 * t + 0] = __floats2half2_rn(v.x * inv, v.y * inv);
    o2[2 * t + 1] = __floats2half2_rn(v.z * inv, v.w * inv);
}

// ---------------------------------------------------------------------------
// Kernel 2: attention.  grid = B * (N/BM) = 512 CTAs, 256 threads.
// S = Qn * Kn^T (fp16 wmma, fp32 acc); softmax with FIXED max = 1;
// P' = exp(s-1) * |x_j|;  O += P' * Kn (V == Kn tile, norm folded into P).
// ---------------------------------------------------------------------------
__global__ void __launch_bounds__(256, 1)
attn_kernel(float* __restrict__ out) {
    extern __shared__ char smem[];
    __half* Qs   = reinterpret_cast<__half*>(smem + OFF_Q);
    __half* Ks   = reinterpret_cast<__half*>(smem + OFF_K);
    float*  Ss   = reinterpret_cast<float*>(smem + OFF_S);
    __half* Ps   = reinterpret_cast<__half*>(smem + OFF_P);
    float*  knrm = reinterpret_cast<float*>(smem + OFF_KN);
    float*  lsh  = reinterpret_cast<float*>(smem + OFF_L);

    const int b  = blockIdx.x / MBLOCKS;
    const int m0 = (blockIdx.x % MBLOCKS) * BM;

    const __half* Xn = xn_g + (size_t)b * N * D;
    const float*  Nv = norm_g + (size_t)b * N;

    const int tid  = threadIdx.x;
    const int warp = tid >> 5;
    const int lane = tid & 31;

    // Load Q tile (64 x 512 halfs) into padded smem
    {
        const int4* src = reinterpret_cast<const int4*>(Xn + (size_t)m0 * D);
        for (int i = tid; i < BM * (D / 8); i += 256) {
            int r = i >> 6, seg = i & 63;                  // 64 int4 per row
            reinterpret_cast<int4*>(Qs + r * QLD)[seg] = src[i];
        }
    }
    if (tid < BM) lsh[tid] = 0.0f;

    // Per-warp output accumulators: warp owns D-slice [warp*64, warp*64+64)
    wmma::fragment<wmma::accumulator, 16, 16, 16, float> ofrag[4][4];
    #pragma unroll
    for (int ri = 0; ri < 4; ri++)
        #pragma unroll
        for (int ci = 0; ci < 4; ci++)
            wmma::fill_fragment(ofrag[ri][ci], 0.0f);

    const int sr0 = (warp >> 1) * 16;   // S rows this warp computes
    const int sc0 = (warp & 1) * 32;    // S cols this warp computes
    const int d0  = warp * 64;          // O column slice

    for (int n0 = 0; n0 < N; n0 += BN) {
        __syncthreads();   // prior PV reads of Ks done (and Q/l init on iter 0)

        // Load K tile + key norms
        {
            const int4* src = reinterpret_cast<const int4*>(Xn + (size_t)n0 * D);
            for (int i = tid; i < BN * (D / 8); i += 256) {
                int r = i >> 6, seg = i & 63;
                reinterpret_cast<int4*>(Ks + r * QLD)[seg] = src[i];
            }
            if (tid < BN) knrm[tid] = Nv[n0 + tid];
        }
        __syncthreads();

        // ---- S = Qn * Kn^T : each warp a 16x32 piece ----
        {
            wmma::fragment<wmma::accumulator, 16, 16, 16, float> sacc[2];
            wmma::fill_fragment(sacc[0], 0.0f);
            wmma::fill_fragment(sacc[1], 0.0f);
            for (int k = 0; k < D; k += 16) {
                wmma::fragment<wmma::matrix_a, 16, 16, 16, __half, wmma::row_major> af;
                wmma::load_matrix_sync(af, Qs + sr0 * QLD + k, QLD);
                #pragma unroll
                for (int cc = 0; cc < 2; cc++) {
                    wmma::fragment<wmma::matrix_b, 16, 16, 16, __half, wmma::col_major> bf;
                    wmma::load_matrix_sync(bf, Ks + (sc0 + cc * 16) * QLD + k, QLD);
                    wmma::mma_sync(sacc[cc], af, bf, sacc[cc]);
                }
            }
            wmma::store_matrix_sync(Ss + sr0 * SLD + sc0,      sacc[0], SLD, wmma::mem_row_major);
            wmma::store_matrix_sync(Ss + sr0 * SLD + sc0 + 16, sacc[1], SLD, wmma::mem_row_major);
        }
        __syncthreads();

        // ---- exp(s-1), accumulate l, P = e * |x_j| (fp16) ----
        {
            const int r = tid >> 2;
            const int cseg = (tid & 3) * 16;
            float sum = 0.0f;
            #pragma unroll
            for (int c = 0; c < 16; c++) {
                float s = Ss[r * SLD + cseg + c];
                float e = __expf(s - 1.0f);
                sum += e;
                Ps[r * PLD + cseg + c] = __float2half(e * knrm[cseg + c]);
            }
            sum += __shfl_down_sync(0xffffffffu, sum, 2, 4);
            sum += __shfl_down_sync(0xffffffffu, sum, 1, 4);
            if ((tid & 3) == 0) lsh[r] += sum;   // single writer per row
        }
        __syncthreads();

        // ---- O += P * V  (V = Kn tile, norm already folded into P) ----
        #pragma unroll
        for (int kk = 0; kk < BN; kk += 16) {
            wmma::fragment<wmma::matrix_a, 16, 16, 16, __half, wmma::row_major> af[4];
            wmma::fragment<wmma::matrix_b, 16, 16, 16, __half, wmma::row_major> bf[4];
            #pragma unroll
            for (int ri = 0; ri < 4; ri++)
                wmma::load_matrix_sync(af[ri], Ps + (ri * 16) * PLD + kk, PLD);
            #pragma unroll
            for (int ci = 0; ci < 4; ci++)
                wmma::load_matrix_sync(bf[ci], Ks + kk * QLD + d0 + ci * 16, QLD);
            #pragma unroll
            for (int ri = 0; ri < 4; ri++)
                #pragma unroll
                for (int ci = 0; ci < 4; ci++)
                    wmma::mma_sync(ofrag[ri][ci], af[ri], bf[ci], ofrag[ri][ci]);
        }
    }
    __syncthreads();   // all tiles done; Q/K smem now free, l final

    // Epilogue: stage O slice in smem (aliases Q/K), divide by l, write fp32
    float* Ost = reinterpret_cast<float*>(smem) + warp * (64 * 64);
    #pragma unroll
    for (int ri = 0; ri < 4; ri++)
        #pragma unroll
        for (int ci = 0; ci < 4; ci++)
            wmma::store_matrix_sync(Ost + ri * 16 * 64 + ci * 16, ofrag[ri][ci],
                                    64, wmma::mem_row_major);
    __syncwarp();

    float* outB = out + ((size_t)b * N + m0) * D;
    for (int i = lane; i < 64 * 16; i += 32) {       // 64 rows * 16 float4
        int r  = i >> 4;
        int c4 = (i & 15) * 4;
        float inv = 1.0f / lsh[r];
        float4 v = *reinterpret_cast<float4*>(Ost + r * 64 + c4);
        v.x *= inv; v.y *= inv; v.z *= inv; v.w *= inv;
        *reinterpret_cast<float4*>(outB + (size_t)r * D + d0 + c4) = v;
    }
}

// ---------------------------------------------------------------------------
extern "C" void kernel_launch(void* const* d_in, const int* in_sizes, int n_in,
                              void* d_out, int out_size) {
    (void)in_sizes; (void)n_in; (void)out_size;
    const float* x = reinterpret_cast<const float*>(d_in[0]);
    float* out = reinterpret_cast<float*>(d_out);

    cudaFuncSetAttribute(attn_kernel,
                         cudaFuncAttributeMaxDynamicSharedMemorySize, SMEM_BYTES);

    normalize_kernel<<<B * N, 128>>>(x);
    attn_kernel<<<B * MBLOCKS, 256, SMEM_BYTES>>>(out);
}

// round 7
// speedup vs baseline: 1.1426x; 1.1426x over previous
#include <cuda_runtime.h>
#include <cuda_fp16.h>
#include <mma.h>
#include <cstdint>

using namespace nvcuda;

// Problem shape
constexpr int B = 16;
constexpr int N = 2048;
constexpr int D = 512;

// Tiling
constexpr int BM = 64;
constexpr int BN = 64;
constexpr int NT = N / BN;       // 32 key tiles
constexpr int MBLOCKS = N / BM;  // 32

// Padded smem leading dims
constexpr int QLD = D + 8;    // 520 halfs -> 1040B rows (breaks ldmatrix conflicts)
constexpr int SLD = BN + 4;   // 68 floats
constexpr int PLD = BN + 8;   // 72 halfs

// Shared memory layout (bytes)
constexpr int OFF_Q  = 0;
constexpr int SZ_T   = BM * QLD * 2;            // 66560 per Q/K tile
constexpr int OFF_K0 = OFF_Q + SZ_T;            // 66560
constexpr int OFF_K1 = OFF_K0 + SZ_T;           // 133120
constexpr int OFF_S  = OFF_K1 + SZ_T;           // 199680
constexpr int OFF_P  = OFF_S + BM * SLD * 4;    // 217088
constexpr int OFF_KN = OFF_P + BM * PLD * 2;    // 226304
constexpr int OFF_L  = OFF_KN + 256;            // 226560
constexpr int SMEM_BYTES = OFF_L + 256;         // 226816  (<= 232448 limit)
// Epilogue O staging aliases Q+K0: 8 warps * 64*64 floats = 131072 <= 133120. OK.

// Scratch: normalized x (fp16) and per-row L2 norms
__device__ __half xn_g[(size_t)B * N * D];
__device__ float  norm_g[B * N];

__device__ __forceinline__ void cpasync16(uint32_t dst, const void* src) {
    asm volatile("cp.async.cg.shared.global [%0], [%1], 16;" :: "r"(dst), "l"(src));
}
__device__ __forceinline__ void cp_commit() { asm volatile("cp.async.commit_group;"); }
template <int K> __device__ __forceinline__ void cp_wait() {
    asm volatile("cp.async.wait_group %0;" :: "n"(K));
}

// ---------------------------------------------------------------------------
// Kernel 1: per-row L2 norm + fp16 normalize.  grid = B*N blocks, 128 threads.
// ---------------------------------------------------------------------------
__global__ void normalize_kernel(const float* __restrict__ x) {
    const int row = blockIdx.x;
    const float* xr = x + (size_t)row * D;
    const int t = threadIdx.x;

    float4 v = reinterpret_cast<const float4*>(xr)[t];
    float s = v.x * v.x + v.y * v.y + v.z * v.z + v.w * v.w;
    #pragma unroll
    for (int o = 16; o > 0; o >>= 1) s += __shfl_down_sync(0xffffffffu, s, o);

    __shared__ float ws[4];
    __shared__ float inv_sh;
    if ((t & 31) == 0) ws[t >> 5] = s;
    __syncthreads();
    if (t == 0) {
        float tot = ws[0] + ws[1] + ws[2] + ws[3];
        float nm = sqrtf(tot);
        norm_g[row] = nm;
        inv_sh = 1.0f / fmaxf(nm, 1e-20f);
    }
    __syncthreads();
    const float inv = inv_sh;

    __half2* o2 = reinterpret_cast<__half2*>(xn_g + (size_t)row * D);
    o2[2 * t + 0] = __floats2half2_rn(v.x * inv, v.y * inv);
    o2[2 * t + 1] = __floats2half2_rn(v.z * inv, v.w * inv);
}

// ---------------------------------------------------------------------------
// Kernel 2: fused attention with cp.async double-buffered K tiles.
// grid = B * (N/BM) = 512 CTAs, 256 threads.
// S = Qn*Kn^T (HMMA fp16/fp32); softmax with FIXED max = 1;
// P' = exp(s-1)*|x_j|; O += P'*Kn.
// ---------------------------------------------------------------------------
__global__ void __launch_bounds__(256, 1)
attn_kernel(float* __restrict__ out) {
    extern __shared__ char smem[];
    __half* Qs   = reinterpret_cast<__half*>(smem + OFF_Q);
    float*  Ss   = reinterpret_cast<float*>(smem + OFF_S);
    __half* Ps   = reinterpret_cast<__half*>(smem + OFF_P);
    float*  knrm = reinterpret_cast<float*>(smem + OFF_KN);
    float*  lsh  = reinterpret_cast<float*>(smem + OFF_L);

    const uint32_t sK[2] = {
        (uint32_t)__cvta_generic_to_shared(smem + OFF_K0),
        (uint32_t)__cvta_generic_to_shared(smem + OFF_K1)
    };

    const int b  = blockIdx.x / MBLOCKS;
    const int m0 = (blockIdx.x % MBLOCKS) * BM;

    const __half* Xn = xn_g + (size_t)b * N * D;
    const float*  Nv = norm_g + (size_t)b * N;

    const int tid  = threadIdx.x;
    const int warp = tid >> 5;
    const int lane = tid & 31;

    // Load Q tile (64 x 512 halfs) into padded smem (regular loads, once)
    {
        const int4* src = reinterpret_cast<const int4*>(Xn + (size_t)m0 * D);
        for (int i = tid; i < BM * (D / 8); i += 256) {
            int r = i >> 6, seg = i & 63;
            reinterpret_cast<int4*>(Qs + r * QLD)[seg] = src[i];
        }
    }
    if (tid < BM) lsh[tid] = 0.0f;

    // cp.async K-tile loader: 64 rows * 64 segs of 16B, 16 per thread
    auto load_K = [&](int n0, int buf) {
        const char* src = reinterpret_cast<const char*>(Xn + (size_t)n0 * D);
        uint32_t dst = sK[buf];
        #pragma unroll
        for (int k = 0; k < 16; k++) {
            int i = tid + k * 256;
            int r = i >> 6, seg = i & 63;
            cpasync16(dst + r * (QLD * 2) + seg * 16,
                      src + (size_t)r * (D * 2) + seg * 16);
        }
    };

    // Per-warp output accumulators: warp owns D-slice [warp*64, warp*64+64)
    wmma::fragment<wmma::accumulator, 16, 16, 16, float> ofrag[4][4];
    #pragma unroll
    for (int ri = 0; ri < 4; ri++)
        #pragma unroll
        for (int ci = 0; ci < 4; ci++)
            wmma::fill_fragment(ofrag[ri][ci], 0.0f);

    const int sr0 = (warp >> 1) * 16;
    const int sc0 = (warp & 1) * 32;
    const int d0  = warp * 64;

    // Preload tile 0
    load_K(0, 0);
    cp_commit();

    for (int t = 0; t < NT; t++) {
        const int n0 = t * BN;
        __syncthreads();                 // PV readers of buf[(t+1)&1] (tile t-1) done

        // Prefetch next tile into the other buffer
        if (t + 1 < NT) {
            load_K((t + 1) * BN, (t + 1) & 1);
            cp_commit();
            cp_wait<1>();                // tile t's group complete
        } else {
            cp_wait<0>();
        }

        // Prefetch key norms for this tile (consumed after S phase)
        float knv = 0.0f;
        if (tid < BN) knv = __ldg(&Nv[n0 + tid]);

        __syncthreads();                 // all threads' cp.async data visible

        const __half* Ks = reinterpret_cast<const __half*>(
            smem + (((t & 1) == 0) ? OFF_K0 : OFF_K1));

        // ---- S = Qn * Kn^T : each warp a 16x32 piece ----
        {
            wmma::fragment<wmma::accumulator, 16, 16, 16, float> sacc[2];
            wmma::fill_fragment(sacc[0], 0.0f);
            wmma::fill_fragment(sacc[1], 0.0f);
            for (int k = 0; k < D; k += 16) {
                wmma::fragment<wmma::matrix_a, 16, 16, 16, __half, wmma::row_major> af;
                wmma::load_matrix_sync(af, Qs + sr0 * QLD + k, QLD);
                #pragma unroll
                for (int cc = 0; cc < 2; cc++) {
                    wmma::fragment<wmma::matrix_b, 16, 16, 16, __half, wmma::col_major> bf;
                    wmma::load_matrix_sync(bf, Ks + (sc0 + cc * 16) * QLD + k, QLD);
                    wmma::mma_sync(sacc[cc], af, bf, sacc[cc]);
                }
            }
            wmma::store_matrix_sync(Ss + sr0 * SLD + sc0,      sacc[0], SLD, wmma::mem_row_major);
            wmma::store_matrix_sync(Ss + sr0 * SLD + sc0 + 16, sacc[1], SLD, wmma::mem_row_major);
        }
        if (tid < BN) knrm[tid] = knv;
        __syncthreads();

        // ---- exp(s-1), accumulate l, P = e * |x_j| (fp16) ----
        {
            const int r = tid >> 2;
            const int cseg = (tid & 3) * 16;
            float sum = 0.0f;
            #pragma unroll
            for (int c = 0; c < 16; c++) {
                float s = Ss[r * SLD + cseg + c];
                float e = __expf(s - 1.0f);
                sum += e;
                Ps[r * PLD + cseg + c] = __float2half(e * knrm[cseg + c]);
            }
            sum += __shfl_down_sync(0xffffffffu, sum, 2, 4);
            sum += __shfl_down_sync(0xffffffffu, sum, 1, 4);
            if ((tid & 3) == 0) lsh[r] += sum;
        }
        __syncthreads();

        // ---- O += P * V  (V = Kn tile, norms folded into P) ----
        #pragma unroll
        for (int kk = 0; kk < BN; kk += 16) {
            wmma::fragment<wmma::matrix_a, 16, 16, 16, __half, wmma::row_major> af[4];
            wmma::fragment<wmma::matrix_b, 16, 16, 16, __half, wmma::row_major> bf[4];
            #pragma unroll
            for (int ri = 0; ri < 4; ri++)
                wmma::load_matrix_sync(af[ri], Ps + (ri * 16) * PLD + kk, PLD);
            #pragma unroll
            for (int ci = 0; ci < 4; ci++)
                wmma::load_matrix_sync(bf[ci], Ks + kk * QLD + d0 + ci * 16, QLD);
            #pragma unroll
            for (int ri = 0; ri < 4; ri++)
                #pragma unroll
                for (int ci = 0; ci < 4; ci++)
                    wmma::mma_sync(ofrag[ri][ci], af[ri], bf[ci], ofrag[ri][ci]);
        }
    }
    __syncthreads();   // all tiles done; Q/K smem free, l final

    // Epilogue: stage O slice in smem (aliases Q/K0), divide by l, write fp32
    float* Ost = reinterpret_cast<float*>(smem) + warp * (64 * 64);
    #pragma unroll
    for (int ri = 0; ri < 4; ri++)
        #pragma unroll
        for (int ci = 0; ci < 4; ci++)
            wmma::store_matrix_sync(Ost + ri * 16 * 64 + ci * 16, ofrag[ri][ci],
                                    64, wmma::mem_row_major);
    __syncwarp();

    float* outB = out + ((size_t)b * N + m0) * D;
    for (int i = lane; i < 64 * 16; i += 32) {
        int r  = i >> 4;
        int c4 = (i & 15) * 4;
        float inv = 1.0f / lsh[r];
        float4 v = *reinterpret_cast<float4*>(Ost + r * 64 + c4);
        v.x *= inv; v.y *= inv; v.z *= inv; v.w *= inv;
        *reinterpret_cast<float4*>(outB + (size_t)r * D + d0 + c4) = v;
    }
}

// ---------------------------------------------------------------------------
extern "C" void kernel_launch(void* const* d_in, const int* in_sizes, int n_in,
                              void* d_out, int out_size) {
    (void)in_sizes; (void)n_in; (void)out_size;
    const float* x = reinterpret_cast<const float*>(d_in[0]);
    float* out = reinterpret_cast<float*>(d_out);

    cudaFuncSetAttribute(attn_kernel,
                         cudaFuncAttributeMaxDynamicSharedMemorySize, SMEM_BYTES);

    normalize_kernel<<<B * N, 128>>>(x);
    attn_kernel<<<B * MBLOCKS, 256, SMEM_BYTES>>>(out);
}